// round 14
// baseline (speedup 1.0000x reference)
#include <cuda_runtime.h>
#include <cuda_fp16.h>

// B=2, S=2048, D=1024, H=16, HS=64
// out = V @ (K^T @ V) / 8 per (b,h)   (no softmax, Q==V)
// R14: ldmatrix fragment loads (1 instr per fragment) from NATURAL K-major
// fp16 layout; pair-permutation machinery deleted everywhere. Pitch 144B
// (=16 mod 128) makes every ldmatrix conflict-free.
//   Y[b] = Vcat[b] @ G[b],  G[b][(h,e),n] = sum_f M[b,h,e,f] Wp[h*64+f,n]

#define S_LEN 2048
#define D_DIM 1024
#define HS    64
#define BH    32
#define MROWS 4096

// ---------------- scratch (no allocs allowed) ----------------
__device__ __half g_Kh[BH * S_LEN * HS];       // [B,H,S,HS] fp16
__device__ float  g_M[BH * HS * HS];           // K^T V / 8 (atomic accum)
__device__ __half g_Ah[MROWS * D_DIM];         // Vcat: [b,s,(h,e)] fp16
__device__ __half g_Xh[MROWS * D_DIM];         // x fp16
__device__ __half g_Wth[2048 * 1024];          // [Wk|Wv] K-major rows
__device__ __half g_Wpth[1024 * 1024];         // Wproj^T K-major rows
__device__ __half g_Gt[2 * 1024 * 1024];       // G[b]: rows n, k=(h,e)

// =============================================================
// helpers
// =============================================================
__device__ __forceinline__ unsigned smem_u32(const void* p) {
    unsigned a;
    asm("{ .reg .u64 t; cvta.to.shared.u64 t, %1; cvt.u32.u64 %0, t; }"
        : "=r"(a) : "l"(p));
    return a;
}

__device__ __forceinline__ void cp16(void* dst, const void* src) {
    unsigned d;
    asm("{ .reg .u64 t; cvta.to.shared.u64 t, %1; cvt.u32.u64 %0, t; }"
        : "=r"(d) : "l"(dst));
    asm volatile("cp.async.cg.shared.global [%0], [%1], 16;" :: "r"(d), "l"(src));
}

__device__ __forceinline__ void ldsm4(unsigned* r, unsigned addr) {
    asm volatile("ldmatrix.sync.aligned.m8n8.x4.shared.b16 {%0,%1,%2,%3}, [%4];"
        : "=r"(r[0]), "=r"(r[1]), "=r"(r[2]), "=r"(r[3]) : "r"(addr));
}

__device__ __forceinline__ void mma16(float* d, const unsigned* a, const unsigned* b) {
    asm volatile(
        "mma.sync.aligned.m16n8k16.row.col.f32.f16.f16.f32 "
        "{%0,%1,%2,%3}, {%4,%5,%6,%7}, {%8,%9}, {%0,%1,%2,%3};"
        : "+f"(d[0]), "+f"(d[1]), "+f"(d[2]), "+f"(d[3])
        : "r"(a[0]), "r"(a[1]), "r"(a[2]), "r"(a[3]), "r"(b[0]), "r"(b[1]));
}

// =============================================================
// prep: fused xcvt + tW + tWp + g_M zeroing, dispatched by block range.
// All outputs NATURAL layout fp16.
// =============================================================
__global__ __launch_bounds__(256) void prep(const float* __restrict__ x,
                                            const float* __restrict__ Wk,
                                            const float* __restrict__ Wv,
                                            const float* __restrict__ Wp)
{
    __shared__ float tile[32][33];
    const int blk = blockIdx.x, tid = threadIdx.x;

    if (blk < 1024) {                       // ---- x -> fp16 ----
        int base = (blk * 256 + tid) * 16;
        float v[16];
        #pragma unroll
        for (int i = 0; i < 4; i++)
            *(float4*)(v + 4 * i) = *(const float4*)(x + base + 4 * i);
        __half2 out[8];
        #pragma unroll
        for (int p = 0; p < 8; p++)
            out[p] = __floats2half2_rn(v[2 * p], v[2 * p + 1]);
        *(uint4*)(g_Xh + base)     = ((uint4*)out)[0];
        *(uint4*)(g_Xh + base + 8) = ((uint4*)out)[1];
    } else if (blk < 3072) {                // ---- tW ----
        const int local = blk - 1024;
        const int bx = local & 31, by = (local >> 5) & 1, hh = local >> 6;
        const int x0 = bx * 32, y0 = by * 32;
        const int tx = tid & 31, ty = tid >> 5;
        const float* W = (hh < 16) ? Wk : Wv;
        const int h = hh & 15;
        #pragma unroll
        for (int j = 0; j < 4; j++)
            tile[ty + 8 * j][tx] = W[h * 65536 + (x0 + ty + 8 * j) * 64 + y0 + tx];
        __syncthreads();
        #pragma unroll
        for (int j = 0; j < 4; j++)
            g_Wth[(hh * 64 + y0 + ty + 8 * j) * 1024 + x0 + tx] =
                __float2half_rn(tile[tx][ty + 8 * j]);
    } else if (blk < 4096) {                // ---- tWp ----
        const int local = blk - 3072;
        const int bx = local & 31, by = local >> 5;
        const int x0 = bx * 32, y0 = by * 32;
        const int tx = tid & 31, ty = tid >> 5;
        #pragma unroll
        for (int j = 0; j < 4; j++)
            tile[ty + 8 * j][tx] = Wp[(y0 + ty + 8 * j) * 1024 + x0 + tx];
        __syncthreads();
        #pragma unroll
        for (int j = 0; j < 4; j++)
            g_Wpth[(x0 + ty + 8 * j) * 1024 + y0 + tx] =
                __float2half_rn(tile[tx][ty + 8 * j]);
    } else {                                // ---- zero g_M ----
        g_M[(blk - 4096) * 256 + tid] = 0.f;
    }
}

// =============================================================
// fp16 mma.sync GEMM: C[4096, N] = A[4096,1024] @ B^T (B = K-major rows)
// BM=128, BN=256, BK=64 halves, 3-stage / distance-2 prefetch, one sync/iter.
// Fragments via ldmatrix.x4 from natural layout, pitch 144B (conflict-free).
// mode 0: A=g_Xh, B=g_Wth; epilogue scatters K + Vcat (both natural).
// mode 1: A=g_Ah (Vcat), B=g_Gt[b], writes Y + bias.
// =============================================================
#define BMt 128
#define BNt 256
#define BKh 64
#define PITCHB 144                              // 128B data + 16B pad
#define SA_BYTES (BMt * PITCHB)                 // 18432
#define SB_BYTES (BNt * PITCHB)                 // 36864
#define STAGE_BYTES (SA_BYTES + SB_BYTES)       // 55296
#define GEMM_SMEM (3 * STAGE_BYTES)             // 165888

__global__ __launch_bounds__(256, 1)
void gemm_mma(const float* __restrict__ bias,
              float* __restrict__ Y,
              int mode)
{
    extern __shared__ __align__(16) char sm[];
    const int tid = threadIdx.x, wid = tid >> 5, lane = tid & 31;
    const int g = lane >> 2, tg = lane & 3;
    const int bm = blockIdx.y * BMt, bn = blockIdx.x * BNt;
    const unsigned smbase = smem_u32(sm);

    const __half* Ag = ((mode == 0) ? g_Xh : g_Ah) + (size_t)bm * 1024;
    const __half* Bg = ((mode == 0) ? g_Wth
                                    : g_Gt + (size_t)(bm >> 11) * 1048576)
                       + (size_t)bn * 1024;

    auto prefetch = [&](int kc) {
        char* sA = sm + (kc % 3) * STAGE_BYTES;
        char* sB = sA + SA_BYTES;
        const __half* As = Ag + kc * BKh;
        const __half* Bs = Bg + kc * BKh;
        #pragma unroll
        for (int i = 0; i < 4; i++) {
            int idx = tid + i * 256;
            int m = idx >> 3, c8 = idx & 7;
            cp16(sA + m * PITCHB + c8 * 16, As + (size_t)m * 1024 + c8 * 8);
        }
        #pragma unroll
        for (int i = 0; i < 8; i++) {
            int idx = tid + i * 256;
            int n = idx >> 3, c8 = idx & 7;
            cp16(sB + n * PITCHB + c8 * 16, Bs + (size_t)n * 1024 + c8 * 8);
        }
        asm volatile("cp.async.commit_group;" ::: "memory");
    };

    prefetch(0); prefetch(1);

    const int wm = (wid & 1) * 64;
    const int wn = (wid >> 1) * 64;

    // ldmatrix per-thread address components
    const int j8  = lane & 7, grp = lane >> 3;
    const int arow = (grp & 1) * 8 + j8;       // A: tiles (g,k0),(g+8,k0),(g,k8),(g+8,k8)
    const int acol = (grp >> 1) * 8;
    const int brow = (grp >> 1) * 8 + j8;      // B: tiles (n0,k0),(n0,k8),(n8,k0),(n8,k8)
    const int bcol = (grp & 1) * 8;

    float acc[4][8][4];
    #pragma unroll
    for (int mt = 0; mt < 4; mt++)
        #pragma unroll
        for (int nt = 0; nt < 8; nt++)
            #pragma unroll
            for (int q = 0; q < 4; q++) acc[mt][nt][q] = 0.f;

    for (int kc = 0; kc < 16; kc++) {
        const unsigned sAu = smbase + (kc % 3) * STAGE_BYTES;
        const unsigned sBu = sAu + SA_BYTES;
        if (kc < 15) asm volatile("cp.async.wait_group 1;" ::: "memory");
        else         asm volatile("cp.async.wait_group 0;" ::: "memory");
        __syncthreads();
        if (kc + 2 < 16) prefetch(kc + 2);

        #pragma unroll
        for (int ks = 0; ks < 4; ks++) {
            const int k0 = ks * 16;
            unsigned a[4][4], bq[4][4];
            #pragma unroll
            for (int mt = 0; mt < 4; mt++)
                ldsm4(a[mt], sAu + (wm + mt * 16 + arow) * PITCHB + (k0 + acol) * 2);
            #pragma unroll
            for (int p = 0; p < 4; p++)
                ldsm4(bq[p], sBu + (wn + p * 16 + brow) * PITCHB + (k0 + bcol) * 2);
            #pragma unroll
            for (int mt = 0; mt < 4; mt++)
                #pragma unroll
                for (int nt = 0; nt < 8; nt++)
                    mma16(acc[mt][nt], a[mt], &bq[nt >> 1][(nt & 1) * 2]);
        }
    }

    // ---- epilogue ----
    // C frag: c0 (row g, col 2tg), c1 (+1), c2 (row g+8, col 2tg), c3 (+1)
    const int gnw = bn + wn;                 // 64-aligned -> exactly 1 head
    if (mode == 0) {
        const int isK = (gnw < 1024);
        const int h = (gnw & 1023) >> 6;
        #pragma unroll
        for (int mt = 0; mt < 4; mt++) {
            const int m0 = bm + wm + mt * 16 + g;
            #pragma unroll
            for (int half = 0; half < 2; half++) {
                const int m = m0 + half * 8;
                const int b = m >> 11, s = m & 2047;
                __half* dst = isK ? (g_Kh + (size_t)((b * 16 + h) * 2048 + s) * 64)
                                  : (g_Ah + (size_t)(b * 2048 + s) * 1024 + h * 64);
                #pragma unroll
                for (int nt = 0; nt < 8; nt++) {
                    const int e = nt * 8 + tg * 2;
                    *(__half2*)(dst + e) =
                        __floats2half2_rn(acc[mt][nt][half * 2],
                                          acc[mt][nt][half * 2 + 1]);
                }
            }
        }
    } else {
        #pragma unroll
        for (int mt = 0; mt < 4; mt++) {
            const int m0 = bm + wm + mt * 16 + g;
            #pragma unroll
            for (int half = 0; half < 2; half++) {
                const int m = m0 + half * 8;
                float* dst = Y + (size_t)m * 1024;
                #pragma unroll
                for (int nt = 0; nt < 8; nt++) {
                    const int gn = gnw + nt * 8 + tg * 2;
                    float2 bb = *(const float2*)(bias + gn);
                    *(float2*)(dst + gn) = make_float2(acc[mt][nt][half * 2] + bb.x,
                                                       acc[mt][nt][half * 2 + 1] + bb.y);
                }
            }
        }
    }
}

// =============================================================
// Kernel 2: per-(b,h) partial M = K^T V over an S-chunk of 256 rows.
// K from g_Kh, V from Vcat (g_Ah) — both natural fp16 now.
// atomicAdd into g_M with the 1/8 scale folded in.
// =============================================================
__global__ __launch_bounds__(256) void k2_kv()
{
    const int bh = blockIdx.x;
    const int b = bh >> 4, h = bh & 15;
    const int sc = blockIdx.y;
    const __half* K  = g_Kh + (size_t)(bh * S_LEN + sc * 256) * HS;
    const __half* Vc = g_Ah + (size_t)(b * S_LEN + sc * 256) * 1024 + h * 64;

    __shared__ float Ks[32][64];
    __shared__ float Vs[32][64];
    const int tid = threadIdx.x;
    const int tx = tid & 15, ty = tid >> 4;

    float acc[4][4] = {};

    for (int s0 = 0; s0 < 256; s0 += 32) {
        {
            int idx = tid * 8;
            int r = idx >> 6, c = idx & 63;
            uint4 kr = *(const uint4*)(K + (s0 + r) * HS + c);
            uint4 vr = *(const uint4*)(Vc + (size_t)(s0 + r) * 1024 + c);
            const __half2* kh = (const __half2*)&kr;
            const __half2* vh = (const __half2*)&vr;
            #pragma unroll
            for (int q = 0; q < 4; q++) {
                float2 kf = __half22float2(kh[q]);
                float2 vf = __half22float2(vh[q]);
                Ks[r][c + 2 * q] = kf.x; Ks[r][c + 2 * q + 1] = kf.y;
                Vs[r][c + 2 * q] = vf.x; Vs[r][c + 2 * q + 1] = vf.y;
            }
        }
        __syncthreads();
        #pragma unroll
        for (int s = 0; s < 32; s++) {
            float4 a4 = *(const float4*)&Ks[s][ty * 4];
            float4 b4 = *(const float4*)&Vs[s][tx * 4];
            float a[4] = {a4.x, a4.y, a4.z, a4.w};
            float b[4] = {b4.x, b4.y, b4.z, b4.w};
            #pragma unroll
            for (int i = 0; i < 4; i++)
                #pragma unroll
                for (int j = 0; j < 4; j++)
                    acc[i][j] += a[i] * b[j];
        }
        __syncthreads();
    }

    float* Mb = g_M + bh * 4096;
    #pragma unroll
    for (int i = 0; i < 4; i++)
        #pragma unroll
        for (int j = 0; j < 4; j++)
            atomicAdd(&Mb[(ty * 4 + i) * 64 + tx * 4 + j], acc[i][j] * 0.125f);
}

// =============================================================
// k_g (tensor): G[b][n, h*64+e] = sum_f M[b,h,e,f] * Wp[h*64+f, n]
// A = g_Wpth rows n (natural), B = M staged fp16 natural. ldmatrix frags.
// One 256(n) x 64(e) tile per CTA, k=64. grid (4, 32).
// =============================================================
#define KGP 144                                 // 64 halves (128B) + 16B pad
__global__ __launch_bounds__(256) void k_g()
{
    __shared__ __align__(16) char sa[256 * KGP];   // A: 256 n-rows
    __shared__ __align__(16) char sb[64 * KGP];    // B: 64 e-rows

    const int bh = blockIdx.y;
    const int b = bh >> 4, h = bh & 15;
    const int bn = blockIdx.x * 256;
    const int tid = threadIdx.x, wid = tid >> 5, lane = tid & 31;
    const int g = lane >> 2, tg = lane & 3;

    const __half* Aw = g_Wpth + (size_t)bn * 1024 + h * 64;
    #pragma unroll
    for (int i = 0; i < 8; i++) {
        int idx = tid + i * 256;
        int n = idx >> 3, c8 = idx & 7;
        cp16(sa + n * KGP + c8 * 16, Aw + (size_t)n * 1024 + c8 * 8);
    }
    asm volatile("cp.async.commit_group;" ::: "memory");

    const float* Mg = g_M + bh * 4096;
    #pragma unroll
    for (int i = 0; i < 16; i++) {
        int idx = tid + i * 256;
        int e = idx >> 6, f = idx & 63;
        ((__half*)(sb + e * KGP))[f] = __float2half_rn(Mg[idx]);
    }
    asm volatile("cp.async.wait_group 0;" ::: "memory");
    __syncthreads();

    const int wm = (wid & 3) * 64;       // 4 warps along n
    const int wn = (wid >> 2) * 32;      // 2 warps along e

    const int j8  = lane & 7, grp = lane >> 3;
    const int arow = (grp & 1) * 8 + j8;
    const int acol = (grp >> 1) * 8;
    const int brow = (grp >> 1) * 8 + j8;
    const int bcol = (grp & 1) * 8;
    const unsigned sau = smem_u32(sa), sbu = smem_u32(sb);

    float acc[4][4][4] = {};
    #pragma unroll
    for (int ks = 0; ks < 4; ks++) {
        const int k0 = ks * 16;
        unsigned a[4][4], bq[2][4];
        #pragma unroll
        for (int mt = 0; mt < 4; mt++)
            ldsm4(a[mt], sau + (wm + mt * 16 + arow) * KGP + (k0 + acol) * 2);
        #pragma unroll
        for (int p = 0; p < 2; p++)
            ldsm4(bq[p], sbu + (wn + p * 16 + brow) * KGP + (k0 + bcol) * 2);
        #pragma unroll
        for (int mt = 0; mt < 4; mt++)
            #pragma unroll
            for (int nt = 0; nt < 4; nt++)
                mma16(acc[mt][nt], a[mt], &bq[nt >> 1][(nt & 1) * 2]);
    }

    // epilogue: rows n, cols e -> g_Gt[b][n, h*64 + e] (natural)
    __half* Gb = g_Gt + (size_t)b * 1048576 + h * 64;
    #pragma unroll
    for (int mt = 0; mt < 4; mt++) {
        const int n0 = bn + wm + mt * 16 + g;
        #pragma unroll
        for (int half = 0; half < 2; half++) {
            __half* dst = Gb + (size_t)(n0 + half * 8) * 1024;
            #pragma unroll
            for (int nt = 0; nt < 4; nt++) {
                const int e = wn + nt * 8 + tg * 2;
                *(__half2*)(dst + e) =
                    __floats2half2_rn(acc[mt][nt][half * 2],
                                      acc[mt][nt][half * 2 + 1]);
            }
        }
    }
}

// =============================================================
extern "C" void kernel_launch(void* const* d_in, const int* in_sizes, int n_in,
                              void* d_out, int out_size)
{
    const float* x   = (const float*)d_in[0];
    const float* Wk  = (const float*)d_in[1];
    const float* Wv  = (const float*)d_in[2];
    const float* Wp  = (const float*)d_in[3];
    const float* bp  = (const float*)d_in[4];
    float* Y = (float*)d_out;

    cudaFuncSetAttribute(gemm_mma, cudaFuncAttributeMaxDynamicSharedMemorySize, GEMM_SMEM);

    prep<<<4608, 256>>>(x, Wk, Wv, Wp);                    // fused prep + zero
    gemm_mma<<<dim3(8, 32), 256, GEMM_SMEM>>>(bp, Y, 0);   // K + Vcat
    k2_kv<<<dim3(32, 8), 256>>>();                         // K^T V -> g_M (atomic)
    k_g  <<<dim3(4, 32), 256>>>();                         // G[b] = M @ Wp (tensor)
    gemm_mma<<<dim3(4, 32), 256, GEMM_SMEM>>>(bp, Y, 1);   // Y = Vcat@G + b
}

// round 15
// speedup vs baseline: 1.0193x; 1.0193x over previous
#include <cuda_runtime.h>
#include <cuda_fp16.h>

// B=2, S=2048, D=1024, H=16, HS=64
// out = V @ (K^T @ V) / 8 per (b,h)   (no softmax, Q==V)
// R15: k2 + k_g + g_M fused into one tensor-core kernel k_mg:
//   phase 1: M = K^T V (ldmatrix.trans, k=s), fp32 accum, x1/8 -> smem fp16
//   phase 2: G[b][n,(h,e)] = sum_f Wp[h64+f,n] M[e,f]  (k_g structure)
// GEMMs unchanged (R14). g_M deleted; 4 launches total.

#define S_LEN 2048
#define D_DIM 1024
#define HS    64
#define BH    32
#define MROWS 4096

// ---------------- scratch (no allocs allowed) ----------------
__device__ __half g_Kh[BH * S_LEN * HS];       // [B,H,S,HS] fp16
__device__ __half g_Ah[MROWS * D_DIM];         // Vcat: [b,s,(h,e)] fp16
__device__ __half g_Xh[MROWS * D_DIM];         // x fp16
__device__ __half g_Wth[2048 * 1024];          // [Wk|Wv] K-major rows
__device__ __half g_Wpth[1024 * 1024];         // Wproj^T K-major rows
__device__ __half g_Gt[2 * 1024 * 1024];       // G[b]: rows n, k=(h,e)

// =============================================================
// helpers
// =============================================================
__device__ __forceinline__ unsigned smem_u32(const void* p) {
    unsigned a;
    asm("{ .reg .u64 t; cvta.to.shared.u64 t, %1; cvt.u32.u64 %0, t; }"
        : "=r"(a) : "l"(p));
    return a;
}

__device__ __forceinline__ void cp16(void* dst, const void* src) {
    unsigned d;
    asm("{ .reg .u64 t; cvta.to.shared.u64 t, %1; cvt.u32.u64 %0, t; }"
        : "=r"(d) : "l"(dst));
    asm volatile("cp.async.cg.shared.global [%0], [%1], 16;" :: "r"(d), "l"(src));
}

__device__ __forceinline__ void ldsm4(unsigned* r, unsigned addr) {
    asm volatile("ldmatrix.sync.aligned.m8n8.x4.shared.b16 {%0,%1,%2,%3}, [%4];"
        : "=r"(r[0]), "=r"(r[1]), "=r"(r[2]), "=r"(r[3]) : "r"(addr));
}

__device__ __forceinline__ void ldsm4t(unsigned* r, unsigned addr) {
    asm volatile("ldmatrix.sync.aligned.m8n8.x4.trans.shared.b16 {%0,%1,%2,%3}, [%4];"
        : "=r"(r[0]), "=r"(r[1]), "=r"(r[2]), "=r"(r[3]) : "r"(addr));
}

__device__ __forceinline__ void mma16(float* d, const unsigned* a, const unsigned* b) {
    asm volatile(
        "mma.sync.aligned.m16n8k16.row.col.f32.f16.f16.f32 "
        "{%0,%1,%2,%3}, {%4,%5,%6,%7}, {%8,%9}, {%0,%1,%2,%3};"
        : "+f"(d[0]), "+f"(d[1]), "+f"(d[2]), "+f"(d[3])
        : "r"(a[0]), "r"(a[1]), "r"(a[2]), "r"(a[3]), "r"(b[0]), "r"(b[1]));
}

// =============================================================
// prep: fused xcvt + tW + tWp, dispatched by block range. Natural fp16.
// =============================================================
__global__ __launch_bounds__(256) void prep(const float* __restrict__ x,
                                            const float* __restrict__ Wk,
                                            const float* __restrict__ Wv,
                                            const float* __restrict__ Wp)
{
    __shared__ float tile[32][33];
    const int blk = blockIdx.x, tid = threadIdx.x;

    if (blk < 1024) {                       // ---- x -> fp16 ----
        int base = (blk * 256 + tid) * 16;
        float v[16];
        #pragma unroll
        for (int i = 0; i < 4; i++)
            *(float4*)(v + 4 * i) = *(const float4*)(x + base + 4 * i);
        __half2 out[8];
        #pragma unroll
        for (int p = 0; p < 8; p++)
            out[p] = __floats2half2_rn(v[2 * p], v[2 * p + 1]);
        *(uint4*)(g_Xh + base)     = ((uint4*)out)[0];
        *(uint4*)(g_Xh + base + 8) = ((uint4*)out)[1];
    } else if (blk < 3072) {                // ---- tW ----
        const int local = blk - 1024;
        const int bx = local & 31, by = (local >> 5) & 1, hh = local >> 6;
        const int x0 = bx * 32, y0 = by * 32;
        const int tx = tid & 31, ty = tid >> 5;
        const float* W = (hh < 16) ? Wk : Wv;
        const int h = hh & 15;
        #pragma unroll
        for (int j = 0; j < 4; j++)
            tile[ty + 8 * j][tx] = W[h * 65536 + (x0 + ty + 8 * j) * 64 + y0 + tx];
        __syncthreads();
        #pragma unroll
        for (int j = 0; j < 4; j++)
            g_Wth[(hh * 64 + y0 + ty + 8 * j) * 1024 + x0 + tx] =
                __float2half_rn(tile[tx][ty + 8 * j]);
    } else {                                // ---- tWp ----
        const int local = blk - 3072;
        const int bx = local & 31, by = local >> 5;
        const int x0 = bx * 32, y0 = by * 32;
        const int tx = tid & 31, ty = tid >> 5;
        #pragma unroll
        for (int j = 0; j < 4; j++)
            tile[ty + 8 * j][tx] = Wp[(y0 + ty + 8 * j) * 1024 + x0 + tx];
        __syncthreads();
        #pragma unroll
        for (int j = 0; j < 4; j++)
            g_Wpth[(x0 + ty + 8 * j) * 1024 + y0 + tx] =
                __float2half_rn(tile[tx][ty + 8 * j]);
    }
}

// =============================================================
// fp16 mma.sync GEMM (unchanged from R14)
// =============================================================
#define BMt 128
#define BNt 256
#define BKh 64
#define PITCHB 144
#define SA_BYTES (BMt * PITCHB)
#define SB_BYTES (BNt * PITCHB)
#define STAGE_BYTES (SA_BYTES + SB_BYTES)
#define GEMM_SMEM (3 * STAGE_BYTES)

__global__ __launch_bounds__(256, 1)
void gemm_mma(const float* __restrict__ bias,
              float* __restrict__ Y,
              int mode)
{
    extern __shared__ __align__(16) char sm[];
    const int tid = threadIdx.x, wid = tid >> 5, lane = tid & 31;
    const int g = lane >> 2, tg = lane & 3;
    const int bm = blockIdx.y * BMt, bn = blockIdx.x * BNt;
    const unsigned smbase = smem_u32(sm);

    const __half* Ag = ((mode == 0) ? g_Xh : g_Ah) + (size_t)bm * 1024;
    const __half* Bg = ((mode == 0) ? g_Wth
                                    : g_Gt + (size_t)(bm >> 11) * 1048576)
                       + (size_t)bn * 1024;

    auto prefetch = [&](int kc) {
        char* sA = sm + (kc % 3) * STAGE_BYTES;
        char* sB = sA + SA_BYTES;
        const __half* As = Ag + kc * BKh;
        const __half* Bs = Bg + kc * BKh;
        #pragma unroll
        for (int i = 0; i < 4; i++) {
            int idx = tid + i * 256;
            int m = idx >> 3, c8 = idx & 7;
            cp16(sA + m * PITCHB + c8 * 16, As + (size_t)m * 1024 + c8 * 8);
        }
        #pragma unroll
        for (int i = 0; i < 8; i++) {
            int idx = tid + i * 256;
            int n = idx >> 3, c8 = idx & 7;
            cp16(sB + n * PITCHB + c8 * 16, Bs + (size_t)n * 1024 + c8 * 8);
        }
        asm volatile("cp.async.commit_group;" ::: "memory");
    };

    prefetch(0); prefetch(1);

    const int wm = (wid & 1) * 64;
    const int wn = (wid >> 1) * 64;

    const int j8  = lane & 7, grp = lane >> 3;
    const int arow = (grp & 1) * 8 + j8;
    const int acol = (grp >> 1) * 8;
    const int brow = (grp >> 1) * 8 + j8;
    const int bcol = (grp & 1) * 8;

    float acc[4][8][4];
    #pragma unroll
    for (int mt = 0; mt < 4; mt++)
        #pragma unroll
        for (int nt = 0; nt < 8; nt++)
            #pragma unroll
            for (int q = 0; q < 4; q++) acc[mt][nt][q] = 0.f;

    for (int kc = 0; kc < 16; kc++) {
        const unsigned sAu = smbase + (kc % 3) * STAGE_BYTES;
        const unsigned sBu = sAu + SA_BYTES;
        if (kc < 15) asm volatile("cp.async.wait_group 1;" ::: "memory");
        else         asm volatile("cp.async.wait_group 0;" ::: "memory");
        __syncthreads();
        if (kc + 2 < 16) prefetch(kc + 2);

        #pragma unroll
        for (int ks = 0; ks < 4; ks++) {
            const int k0 = ks * 16;
            unsigned a[4][4], bq[4][4];
            #pragma unroll
            for (int mt = 0; mt < 4; mt++)
                ldsm4(a[mt], sAu + (wm + mt * 16 + arow) * PITCHB + (k0 + acol) * 2);
            #pragma unroll
            for (int p = 0; p < 4; p++)
                ldsm4(bq[p], sBu + (wn + p * 16 + brow) * PITCHB + (k0 + bcol) * 2);
            #pragma unroll
            for (int mt = 0; mt < 4; mt++)
                #pragma unroll
                for (int nt = 0; nt < 8; nt++)
                    mma16(acc[mt][nt], a[mt], &bq[nt >> 1][(nt & 1) * 2]);
        }
    }

    const int gnw = bn + wn;
    if (mode == 0) {
        const int isK = (gnw < 1024);
        const int h = (gnw & 1023) >> 6;
        #pragma unroll
        for (int mt = 0; mt < 4; mt++) {
            const int m0 = bm + wm + mt * 16 + g;
            #pragma unroll
            for (int half = 0; half < 2; half++) {
                const int m = m0 + half * 8;
                const int b = m >> 11, s = m & 2047;
                __half* dst = isK ? (g_Kh + (size_t)((b * 16 + h) * 2048 + s) * 64)
                                  : (g_Ah + (size_t)(b * 2048 + s) * 1024 + h * 64);
                #pragma unroll
                for (int nt = 0; nt < 8; nt++) {
                    const int e = nt * 8 + tg * 2;
                    *(__half2*)(dst + e) =
                        __floats2half2_rn(acc[mt][nt][half * 2],
                                          acc[mt][nt][half * 2 + 1]);
                }
            }
        }
    } else {
        #pragma unroll
        for (int mt = 0; mt < 4; mt++) {
            const int m0 = bm + wm + mt * 16 + g;
            #pragma unroll
            for (int half = 0; half < 2; half++) {
                const int m = m0 + half * 8;
                float* dst = Y + (size_t)m * 1024;
                #pragma unroll
                for (int nt = 0; nt < 8; nt++) {
                    const int gn = gnw + nt * 8 + tg * 2;
                    float2 bb = *(const float2*)(bias + gn);
                    *(float2*)(dst + gn) = make_float2(acc[mt][nt][half * 2] + bb.x,
                                                       acc[mt][nt][half * 2 + 1] + bb.y);
                }
            }
        }
    }
}

// =============================================================
// k_mg: one CTA per (b,h).
// Phase 1: M[e,f] = (1/8) sum_s K[s,e] V[s,f]  via ldmatrix.trans (k = s),
//          32 s-chunks of 64, 3-buffer cp.async. M -> smem fp16 [64][72].
// Phase 2: G[b][n, h*64+e] = sum_f Wp^T[n, h64+f] M[e,f]; 4 n-chunks of 256.
// smem: 3 KV buffers (K 64x144B + V 64x144B = 18432 each) + M (9216);
//       phase-2 Wp chunk (256x144B = 36864) reuses buffer region.
// =============================================================
#define MGP 144
#define KV_BUF 18432
#define SM_M  (3 * KV_BUF)                      // 55296
#define MG_SMEM (SM_M + 9216)                   // 64512

__global__ __launch_bounds__(256, 1) void k_mg()
{
    extern __shared__ __align__(16) char smE[];
    const int bh = blockIdx.x;
    const int b = bh >> 4, h = bh & 15;
    const int tid = threadIdx.x, wid = tid >> 5, lane = tid & 31;
    const int g = lane >> 2, tg = lane & 3;
    const int j8 = lane & 7, grp = lane >> 3;
    const unsigned smbase = smem_u32(smE);

    const __half* Kb = g_Kh + (size_t)bh * S_LEN * HS;
    const __half* Vb = g_Ah + (size_t)b * S_LEN * 1024 + h * 64;

    // ---------------- phase 1: M = K^T V ----------------
    auto prefetch_kv = [&](int sc) {
        char* base = smE + (sc % 3) * KV_BUF;
        #pragma unroll
        for (int i = 0; i < 4; i++) {
            int idx = tid + i * 256;          // 1024: [0,512) K, [512,1024) V
            int mat = idx >> 9, rc = idx & 511;
            int r = rc >> 3, c8 = rc & 7;
            if (mat == 0)
                cp16(base + r * MGP + c8 * 16,
                     Kb + (size_t)(sc * 64 + r) * 64 + c8 * 8);
            else
                cp16(base + 9216 + r * MGP + c8 * 16,
                     Vb + (size_t)(sc * 64 + r) * 1024 + c8 * 8);
        }
        asm volatile("cp.async.commit_group;" ::: "memory");
    };

    prefetch_kv(0); prefetch_kv(1);

    // warp tile: 4 warps along e (16 each), 2 warps along f (32 each)
    const int we = (wid & 3) * 16;
    const int wf = (wid >> 2) * 32;
    // trans-ldmatrix address components
    const int a_s = (grp >> 1) * 8 + j8, a_e = (grp & 1) * 8;   // A = K^T
    const int b_s = (grp & 1) * 8 + j8, b_f = (grp >> 1) * 8;   // B = V^T

    float accM[4][4];
    #pragma unroll
    for (int nt = 0; nt < 4; nt++)
        #pragma unroll
        for (int q = 0; q < 4; q++) accM[nt][q] = 0.f;

    for (int sc = 0; sc < 32; sc++) {
        const unsigned sK = smbase + (sc % 3) * KV_BUF;
        const unsigned sV = sK + 9216;
        if (sc < 31) asm volatile("cp.async.wait_group 1;" ::: "memory");
        else         asm volatile("cp.async.wait_group 0;" ::: "memory");
        __syncthreads();
        if (sc + 2 < 32) prefetch_kv(sc + 2);

        #pragma unroll
        for (int ks = 0; ks < 4; ks++) {
            const int s0 = ks * 16;
            unsigned a[4], bq[2][4];
            ldsm4t(a, sK + (s0 + a_s) * MGP + (we + a_e) * 2);
            #pragma unroll
            for (int p = 0; p < 2; p++)
                ldsm4t(bq[p], sV + (s0 + b_s) * MGP + (wf + p * 16 + b_f) * 2);
            #pragma unroll
            for (int nt = 0; nt < 4; nt++)
                mma16(accM[nt], a, &bq[nt >> 1][(nt & 1) * 2]);
        }
    }

    // write M (x 1/8) to smem fp16 [64][72]
    {
        char* sM = smE + SM_M;
        #pragma unroll
        for (int nt = 0; nt < 4; nt++)
            #pragma unroll
            for (int half = 0; half < 2; half++) {
                const int e = we + g + half * 8;
                const int f = wf + nt * 8 + tg * 2;
                *(__half2*)(sM + e * MGP + f * 2) =
                    __floats2half2_rn(accM[nt][half * 2] * 0.125f,
                                      accM[nt][half * 2 + 1] * 0.125f);
            }
    }
    __syncthreads();

    // ---------------- phase 2: G = Wp^T-rows @ M ----------------
    const __half* Wpb = g_Wpth + h * 64;
    __half* Gb = g_Gt + (size_t)b * 1048576 + h * 64;
    const unsigned sMu = smbase + SM_M;

    const int wm = (wid & 3) * 64;        // 4 warps along n
    const int wn = (wid >> 2) * 32;       // 2 warps along e
    const int arow = (grp & 1) * 8 + j8, acol = (grp >> 1) * 8;  // non-trans A
    const int brow = (grp >> 1) * 8 + j8, bcol = (grp & 1) * 8;  // non-trans B

    for (int nc = 0; nc < 4; nc++) {
        // stage Wp chunk [256 n x 64 f] into buffer region 0
        #pragma unroll
        for (int i = 0; i < 8; i++) {
            int idx = tid + i * 256;
            int r = idx >> 3, c8 = idx & 7;
            cp16(smE + r * MGP + c8 * 16,
                 Wpb + (size_t)(nc * 256 + r) * 1024 + c8 * 8);
        }
        asm volatile("cp.async.commit_group;" ::: "memory");
        asm volatile("cp.async.wait_group 0;" ::: "memory");
        __syncthreads();

        float acc2[4][4][4];
        #pragma unroll
        for (int mt = 0; mt < 4; mt++)
            #pragma unroll
            for (int nt = 0; nt < 4; nt++)
                #pragma unroll
                for (int q = 0; q < 4; q++) acc2[mt][nt][q] = 0.f;

        #pragma unroll
        for (int ks = 0; ks < 4; ks++) {
            const int k0 = ks * 16;
            unsigned a[4][4], bq[2][4];
            #pragma unroll
            for (int mt = 0; mt < 4; mt++)
                ldsm4(a[mt], smbase + (wm + mt * 16 + arow) * MGP + (k0 + acol) * 2);
            #pragma unroll
            for (int p = 0; p < 2; p++)
                ldsm4(bq[p], sMu + (wn + p * 16 + brow) * MGP + (k0 + bcol) * 2);
            #pragma unroll
            for (int mt = 0; mt < 4; mt++)
                #pragma unroll
                for (int nt = 0; nt < 4; nt++)
                    mma16(acc2[mt][nt], a[mt], &bq[nt >> 1][(nt & 1) * 2]);
        }

        #pragma unroll
        for (int mt = 0; mt < 4; mt++) {
            const int n0 = nc * 256 + wm + mt * 16 + g;
            #pragma unroll
            for (int half = 0; half < 2; half++) {
                __half* dst = Gb + (size_t)(n0 + half * 8) * 1024;
                #pragma unroll
                for (int nt = 0; nt < 4; nt++) {
                    const int e = wn + nt * 8 + tg * 2;
                    *(__half2*)(dst + e) =
                        __floats2half2_rn(acc2[mt][nt][half * 2],
                                          acc2[mt][nt][half * 2 + 1]);
                }
            }
        }
        __syncthreads();     // before next chunk overwrites the buffer
    }
}

// =============================================================
extern "C" void kernel_launch(void* const* d_in, const int* in_sizes, int n_in,
                              void* d_out, int out_size)
{
    const float* x   = (const float*)d_in[0];
    const float* Wk  = (const float*)d_in[1];
    const float* Wv  = (const float*)d_in[2];
    const float* Wp  = (const float*)d_in[3];
    const float* bp  = (const float*)d_in[4];
    float* Y = (float*)d_out;

    cudaFuncSetAttribute(gemm_mma, cudaFuncAttributeMaxDynamicSharedMemorySize, GEMM_SMEM);
    cudaFuncSetAttribute(k_mg, cudaFuncAttributeMaxDynamicSharedMemorySize, MG_SMEM);

    prep<<<4096, 256>>>(x, Wk, Wv, Wp);                    // fp16 conversions
    gemm_mma<<<dim3(8, 32), 256, GEMM_SMEM>>>(bp, Y, 0);   // K + Vcat
    k_mg<<<32, 256, MG_SMEM>>>();                          // M then G (fused)
    gemm_mma<<<dim3(4, 32), 256, GEMM_SMEM>>>(bp, Y, 1);   // Y = Vcat@G + b
}

// round 16
// speedup vs baseline: 1.0529x; 1.0330x over previous
#include <cuda_runtime.h>
#include <cuda_fp16.h>

// B=2, S=2048, D=1024, H=16, HS=64
// out = V @ (K^T @ V) / 8 per (b,h)   (no softmax, Q==V)
// R16: occupancy-2 GEMM (BN=128, 110KB smem, <=128 regs). Rationale: R15
// profile shows issue=16% / tensor=40% -> latency-bound, so 4 warps/SMSP
// (vs 2) should fill stall slots. (R8's occ-2 failure was in an
// issue-COUNT-bound kernel; ldmatrix removed that constraint in R14.)
//   Y[b] = Vcat[b] @ G[b],  G[b][(h,e),n] = sum_f M[b,h,e,f] Wp[h*64+f,n]

#define S_LEN 2048
#define D_DIM 1024
#define HS    64
#define BH    32
#define MROWS 4096

// ---------------- scratch (no allocs allowed) ----------------
__device__ __half g_Kh[BH * S_LEN * HS];       // [B,H,S,HS] fp16
__device__ __half g_Ah[MROWS * D_DIM];         // Vcat: [b,s,(h,e)] fp16
__device__ __half g_Xh[MROWS * D_DIM];         // x fp16
__device__ __half g_Wth[2048 * 1024];          // [Wk|Wv] K-major rows
__device__ __half g_Wpth[1024 * 1024];         // Wproj^T K-major rows
__device__ __half g_Gt[2 * 1024 * 1024];       // G[b]: rows n, k=(h,e)

// =============================================================
// helpers
// =============================================================
__device__ __forceinline__ unsigned smem_u32(const void* p) {
    unsigned a;
    asm("{ .reg .u64 t; cvta.to.shared.u64 t, %1; cvt.u32.u64 %0, t; }"
        : "=r"(a) : "l"(p));
    return a;
}

__device__ __forceinline__ void cp16(void* dst, const void* src) {
    unsigned d;
    asm("{ .reg .u64 t; cvta.to.shared.u64 t, %1; cvt.u32.u64 %0, t; }"
        : "=r"(d) : "l"(dst));
    asm volatile("cp.async.cg.shared.global [%0], [%1], 16;" :: "r"(d), "l"(src));
}

__device__ __forceinline__ void ldsm4(unsigned* r, unsigned addr) {
    asm volatile("ldmatrix.sync.aligned.m8n8.x4.shared.b16 {%0,%1,%2,%3}, [%4];"
        : "=r"(r[0]), "=r"(r[1]), "=r"(r[2]), "=r"(r[3]) : "r"(addr));
}

__device__ __forceinline__ void ldsm4t(unsigned* r, unsigned addr) {
    asm volatile("ldmatrix.sync.aligned.m8n8.x4.trans.shared.b16 {%0,%1,%2,%3}, [%4];"
        : "=r"(r[0]), "=r"(r[1]), "=r"(r[2]), "=r"(r[3]) : "r"(addr));
}

__device__ __forceinline__ void mma16(float* d, const unsigned* a, const unsigned* b) {
    asm volatile(
        "mma.sync.aligned.m16n8k16.row.col.f32.f16.f16.f32 "
        "{%0,%1,%2,%3}, {%4,%5,%6,%7}, {%8,%9}, {%0,%1,%2,%3};"
        : "+f"(d[0]), "+f"(d[1]), "+f"(d[2]), "+f"(d[3])
        : "r"(a[0]), "r"(a[1]), "r"(a[2]), "r"(a[3]), "r"(b[0]), "r"(b[1]));
}

// =============================================================
// prep: fused xcvt + tW + tWp, dispatched by block range. Natural fp16.
// =============================================================
__global__ __launch_bounds__(256) void prep(const float* __restrict__ x,
                                            const float* __restrict__ Wk,
                                            const float* __restrict__ Wv,
                                            const float* __restrict__ Wp)
{
    __shared__ float tile[32][33];
    const int blk = blockIdx.x, tid = threadIdx.x;

    if (blk < 1024) {                       // ---- x -> fp16 ----
        int base = (blk * 256 + tid) * 16;
        float v[16];
        #pragma unroll
        for (int i = 0; i < 4; i++)
            *(float4*)(v + 4 * i) = *(const float4*)(x + base + 4 * i);
        __half2 out[8];
        #pragma unroll
        for (int p = 0; p < 8; p++)
            out[p] = __floats2half2_rn(v[2 * p], v[2 * p + 1]);
        *(uint4*)(g_Xh + base)     = ((uint4*)out)[0];
        *(uint4*)(g_Xh + base + 8) = ((uint4*)out)[1];
    } else if (blk < 3072) {                // ---- tW ----
        const int local = blk - 1024;
        const int bx = local & 31, by = (local >> 5) & 1, hh = local >> 6;
        const int x0 = bx * 32, y0 = by * 32;
        const int tx = tid & 31, ty = tid >> 5;
        const float* W = (hh < 16) ? Wk : Wv;
        const int h = hh & 15;
        #pragma unroll
        for (int j = 0; j < 4; j++)
            tile[ty + 8 * j][tx] = W[h * 65536 + (x0 + ty + 8 * j) * 64 + y0 + tx];
        __syncthreads();
        #pragma unroll
        for (int j = 0; j < 4; j++)
            g_Wth[(hh * 64 + y0 + ty + 8 * j) * 1024 + x0 + tx] =
                __float2half_rn(tile[tx][ty + 8 * j]);
    } else {                                // ---- tWp ----
        const int local = blk - 3072;
        const int bx = local & 31, by = local >> 5;
        const int x0 = bx * 32, y0 = by * 32;
        const int tx = tid & 31, ty = tid >> 5;
        #pragma unroll
        for (int j = 0; j < 4; j++)
            tile[ty + 8 * j][tx] = Wp[(y0 + ty + 8 * j) * 1024 + x0 + tx];
        __syncthreads();
        #pragma unroll
        for (int j = 0; j < 4; j++)
            g_Wpth[(x0 + ty + 8 * j) * 1024 + y0 + tx] =
                __float2half_rn(tile[tx][ty + 8 * j]);
    }
}

// =============================================================
// fp16 mma.sync GEMM: C[4096, N] = A[4096,1024] @ B^T (B = K-major rows)
// BM=128, BN=128, BK=64 halves, 3-stage, occ-2 (110.6KB smem, <=128 regs).
// 8 warps: 2 along M (64), 4 along N (32). ldmatrix frags, pitch 144B.
// mode 0: A=g_Xh, B=g_Wth; epilogue scatters K + Vcat.
// mode 1: A=g_Ah (Vcat), B=g_Gt[b], writes Y + bias.
// =============================================================
#define BMt 128
#define BNt 128
#define BKh 64
#define PITCHB 144
#define SA_BYTES (BMt * PITCHB)                 // 18432
#define SB_BYTES (BNt * PITCHB)                 // 18432
#define STAGE_BYTES (SA_BYTES + SB_BYTES)       // 36864
#define GEMM_SMEM (3 * STAGE_BYTES)             // 110592

__global__ __launch_bounds__(256, 2)
void gemm_mma(const float* __restrict__ bias,
              float* __restrict__ Y,
              int mode)
{
    extern __shared__ __align__(16) char sm[];
    const int tid = threadIdx.x, wid = tid >> 5, lane = tid & 31;
    const int g = lane >> 2, tg = lane & 3;
    const int bm = blockIdx.y * BMt, bn = blockIdx.x * BNt;
    const unsigned smbase = smem_u32(sm);

    const __half* Ag = ((mode == 0) ? g_Xh : g_Ah) + (size_t)bm * 1024;
    const __half* Bg = ((mode == 0) ? g_Wth
                                    : g_Gt + (size_t)(bm >> 11) * 1048576)
                       + (size_t)bn * 1024;

    auto prefetch = [&](int kc) {
        char* sA = sm + (kc % 3) * STAGE_BYTES;
        char* sB = sA + SA_BYTES;
        const __half* As = Ag + kc * BKh;
        const __half* Bs = Bg + kc * BKh;
        #pragma unroll
        for (int i = 0; i < 4; i++) {
            int idx = tid + i * 256;
            int m = idx >> 3, c8 = idx & 7;
            cp16(sA + m * PITCHB + c8 * 16, As + (size_t)m * 1024 + c8 * 8);
        }
        #pragma unroll
        for (int i = 0; i < 4; i++) {
            int idx = tid + i * 256;
            int n = idx >> 3, c8 = idx & 7;
            cp16(sB + n * PITCHB + c8 * 16, Bs + (size_t)n * 1024 + c8 * 8);
        }
        asm volatile("cp.async.commit_group;" ::: "memory");
    };

    prefetch(0); prefetch(1);

    const int wm = (wid & 1) * 64;       // 2 warps along M (64 rows)
    const int wn = (wid >> 1) * 32;      // 4 warps along N (32 cols)

    const int j8  = lane & 7, grp = lane >> 3;
    const int arow = (grp & 1) * 8 + j8;
    const int acol = (grp >> 1) * 8;
    const int brow = (grp >> 1) * 8 + j8;
    const int bcol = (grp & 1) * 8;

    float acc[4][4][4];
    #pragma unroll
    for (int mt = 0; mt < 4; mt++)
        #pragma unroll
        for (int nt = 0; nt < 4; nt++)
            #pragma unroll
            for (int q = 0; q < 4; q++) acc[mt][nt][q] = 0.f;

    for (int kc = 0; kc < 16; kc++) {
        const unsigned sAu = smbase + (kc % 3) * STAGE_BYTES;
        const unsigned sBu = sAu + SA_BYTES;
        if (kc < 15) asm volatile("cp.async.wait_group 1;" ::: "memory");
        else         asm volatile("cp.async.wait_group 0;" ::: "memory");
        __syncthreads();
        if (kc + 2 < 16) prefetch(kc + 2);

        #pragma unroll
        for (int ks = 0; ks < 4; ks++) {
            const int k0 = ks * 16;
            unsigned a[4][4], bq[2][4];
            #pragma unroll
            for (int mt = 0; mt < 4; mt++)
                ldsm4(a[mt], sAu + (wm + mt * 16 + arow) * PITCHB + (k0 + acol) * 2);
            #pragma unroll
            for (int p = 0; p < 2; p++)
                ldsm4(bq[p], sBu + (wn + p * 16 + brow) * PITCHB + (k0 + bcol) * 2);
            #pragma unroll
            for (int mt = 0; mt < 4; mt++)
                #pragma unroll
                for (int nt = 0; nt < 4; nt++)
                    mma16(acc[mt][nt], a[mt], &bq[nt >> 1][(nt & 1) * 2]);
        }
    }

    // ---- epilogue ----
    // C frag: c0 (row g, col 2tg), c1 (+1), c2 (row g+8, col 2tg), c3 (+1)
    const int gnw = bn + wn;                 // 32-aligned, inside one head
    if (mode == 0) {
        const int isK = (gnw < 1024);
        const int h  = (gnw & 1023) >> 6;
        const int e0 = gnw & 63;             // 0 or 32: within-head base
        #pragma unroll
        for (int mt = 0; mt < 4; mt++) {
            const int m0 = bm + wm + mt * 16 + g;
            #pragma unroll
            for (int half = 0; half < 2; half++) {
                const int m = m0 + half * 8;
                const int b = m >> 11, s = m & 2047;
                __half* dst = isK
                    ? (g_Kh + (size_t)((b * 16 + h) * 2048 + s) * 64 + e0)
                    : (g_Ah + (size_t)(b * 2048 + s) * 1024 + h * 64 + e0);
                #pragma unroll
                for (int nt = 0; nt < 4; nt++) {
                    const int e = nt * 8 + tg * 2;
                    *(__half2*)(dst + e) =
                        __floats2half2_rn(acc[mt][nt][half * 2],
                                          acc[mt][nt][half * 2 + 1]);
                }
            }
        }
    } else {
        #pragma unroll
        for (int mt = 0; mt < 4; mt++) {
            const int m0 = bm + wm + mt * 16 + g;
            #pragma unroll
            for (int half = 0; half < 2; half++) {
                const int m = m0 + half * 8;
                float* dst = Y + (size_t)m * 1024;
                #pragma unroll
                for (int nt = 0; nt < 4; nt++) {
                    const int gn = gnw + nt * 8 + tg * 2;
                    float2 bb = *(const float2*)(bias + gn);
                    *(float2*)(dst + gn) = make_float2(acc[mt][nt][half * 2] + bb.x,
                                                       acc[mt][nt][half * 2 + 1] + bb.y);
                }
            }
        }
    }
}

// =============================================================
// k_mg: one CTA per (b,h). (unchanged from R15)
// Phase 1: M[e,f] = (1/8) sum_s K[s,e] V[s,f]  via ldmatrix.trans (k = s).
// Phase 2: G[b][n, h*64+e] = sum_f Wp^T[n, h64+f] M[e,f]; 4 n-chunks of 256.
// =============================================================
#define MGP 144
#define KV_BUF 18432
#define SM_M  (3 * KV_BUF)
#define MG_SMEM (SM_M + 9216)

__global__ __launch_bounds__(256, 1) void k_mg()
{
    extern __shared__ __align__(16) char smE[];
    const int bh = blockIdx.x;
    const int b = bh >> 4, h = bh & 15;
    const int tid = threadIdx.x, wid = tid >> 5, lane = tid & 31;
    const int g = lane >> 2, tg = lane & 3;
    const int j8 = lane & 7, grp = lane >> 3;
    const unsigned smbase = smem_u32(smE);

    const __half* Kb = g_Kh + (size_t)bh * S_LEN * HS;
    const __half* Vb = g_Ah + (size_t)b * S_LEN * 1024 + h * 64;

    auto prefetch_kv = [&](int sc) {
        char* base = smE + (sc % 3) * KV_BUF;
        #pragma unroll
        for (int i = 0; i < 4; i++) {
            int idx = tid + i * 256;
            int mat = idx >> 9, rc = idx & 511;
            int r = rc >> 3, c8 = rc & 7;
            if (mat == 0)
                cp16(base + r * MGP + c8 * 16,
                     Kb + (size_t)(sc * 64 + r) * 64 + c8 * 8);
            else
                cp16(base + 9216 + r * MGP + c8 * 16,
                     Vb + (size_t)(sc * 64 + r) * 1024 + c8 * 8);
        }
        asm volatile("cp.async.commit_group;" ::: "memory");
    };

    prefetch_kv(0); prefetch_kv(1);

    const int we = (wid & 3) * 16;
    const int wf = (wid >> 2) * 32;
    const int a_s = (grp >> 1) * 8 + j8, a_e = (grp & 1) * 8;
    const int b_s = (grp & 1) * 8 + j8, b_f = (grp >> 1) * 8;

    float accM[4][4];
    #pragma unroll
    for (int nt = 0; nt < 4; nt++)
        #pragma unroll
        for (int q = 0; q < 4; q++) accM[nt][q] = 0.f;

    for (int sc = 0; sc < 32; sc++) {
        const unsigned sK = smbase + (sc % 3) * KV_BUF;
        const unsigned sV = sK + 9216;
        if (sc < 31) asm volatile("cp.async.wait_group 1;" ::: "memory");
        else         asm volatile("cp.async.wait_group 0;" ::: "memory");
        __syncthreads();
        if (sc + 2 < 32) prefetch_kv(sc + 2);

        #pragma unroll
        for (int ks = 0; ks < 4; ks++) {
            const int s0 = ks * 16;
            unsigned a[4], bq[2][4];
            ldsm4t(a, sK + (s0 + a_s) * MGP + (we + a_e) * 2);
            #pragma unroll
            for (int p = 0; p < 2; p++)
                ldsm4t(bq[p], sV + (s0 + b_s) * MGP + (wf + p * 16 + b_f) * 2);
            #pragma unroll
            for (int nt = 0; nt < 4; nt++)
                mma16(accM[nt], a, &bq[nt >> 1][(nt & 1) * 2]);
        }
    }

    {
        char* sM = smE + SM_M;
        #pragma unroll
        for (int nt = 0; nt < 4; nt++)
            #pragma unroll
            for (int half = 0; half < 2; half++) {
                const int e = we + g + half * 8;
                const int f = wf + nt * 8 + tg * 2;
                *(__half2*)(sM + e * MGP + f * 2) =
                    __floats2half2_rn(accM[nt][half * 2] * 0.125f,
                                      accM[nt][half * 2 + 1] * 0.125f);
            }
    }
    __syncthreads();

    const __half* Wpb = g_Wpth + h * 64;
    __half* Gb = g_Gt + (size_t)b * 1048576 + h * 64;
    const unsigned sMu = smbase + SM_M;

    const int wm = (wid & 3) * 64;
    const int wn = (wid >> 2) * 32;
    const int arow = (grp & 1) * 8 + j8, acol = (grp >> 1) * 8;
    const int brow = (grp >> 1) * 8 + j8, bcol = (grp & 1) * 8;

    for (int nc = 0; nc < 4; nc++) {
        #pragma unroll
        for (int i = 0; i < 8; i++) {
            int idx = tid + i * 256;
            int r = idx >> 3, c8 = idx & 7;
            cp16(smE + r * MGP + c8 * 16,
                 Wpb + (size_t)(nc * 256 + r) * 1024 + c8 * 8);
        }
        asm volatile("cp.async.commit_group;" ::: "memory");
        asm volatile("cp.async.wait_group 0;" ::: "memory");
        __syncthreads();

        float acc2[4][4][4];
        #pragma unroll
        for (int mt = 0; mt < 4; mt++)
            #pragma unroll
            for (int nt = 0; nt < 4; nt++)
                #pragma unroll
                for (int q = 0; q < 4; q++) acc2[mt][nt][q] = 0.f;

        #pragma unroll
        for (int ks = 0; ks < 4; ks++) {
            const int k0 = ks * 16;
            unsigned a[4][4], bq[2][4];
            #pragma unroll
            for (int mt = 0; mt < 4; mt++)
                ldsm4(a[mt], smbase + (wm + mt * 16 + arow) * MGP + (k0 + acol) * 2);
            #pragma unroll
            for (int p = 0; p < 2; p++)
                ldsm4(bq[p], sMu + (wn + p * 16 + brow) * MGP + (k0 + bcol) * 2);
            #pragma unroll
            for (int mt = 0; mt < 4; mt++)
                #pragma unroll
                for (int nt = 0; nt < 4; nt++)
                    mma16(acc2[mt][nt], a[mt], &bq[nt >> 1][(nt & 1) * 2]);
        }

        #pragma unroll
        for (int mt = 0; mt < 4; mt++) {
            const int n0 = nc * 256 + wm + mt * 16 + g;
            #pragma unroll
            for (int half = 0; half < 2; half++) {
                __half* dst = Gb + (size_t)(n0 + half * 8) * 1024;
                #pragma unroll
                for (int nt = 0; nt < 4; nt++) {
                    const int e = wn + nt * 8 + tg * 2;
                    *(__half2*)(dst + e) =
                        __floats2half2_rn(acc2[mt][nt][half * 2],
                                          acc2[mt][nt][half * 2 + 1]);
                }
            }
        }
        __syncthreads();
    }
}

// =============================================================
extern "C" void kernel_launch(void* const* d_in, const int* in_sizes, int n_in,
                              void* d_out, int out_size)
{
    const float* x   = (const float*)d_in[0];
    const float* Wk  = (const float*)d_in[1];
    const float* Wv  = (const float*)d_in[2];
    const float* Wp  = (const float*)d_in[3];
    const float* bp  = (const float*)d_in[4];
    float* Y = (float*)d_out;

    cudaFuncSetAttribute(gemm_mma, cudaFuncAttributeMaxDynamicSharedMemorySize, GEMM_SMEM);
    cudaFuncSetAttribute(k_mg, cudaFuncAttributeMaxDynamicSharedMemorySize, MG_SMEM);

    prep<<<4096, 256>>>(x, Wk, Wv, Wp);                     // fp16 conversions
    gemm_mma<<<dim3(16, 32), 256, GEMM_SMEM>>>(bp, Y, 0);   // K + Vcat
    k_mg<<<32, 256, MG_SMEM>>>();                           // M then G (fused)
    gemm_mma<<<dim3(8, 32), 256, GEMM_SMEM>>>(bp, Y, 1);    // Y = Vcat@G + b
}

// round 17
// speedup vs baseline: 1.0721x; 1.0182x over previous
#include <cuda_runtime.h>
#include <cuda_fp16.h>

// B=2, S=2048, D=1024, H=16, HS=64
// out = V @ (K^T @ V) / 8 per (b,h)   (no softmax, Q==V)
// R17: GEMMs are at the legacy-HMMA dispatch ceiling (~255/265 TF/s measured)
// -> stop touching them. This round recovers serial-chain overhead:
//  - PDL (programmatic dependent launch) on gemm0 -> k_mg -> gemm1
//  - k_mg phase-2 Wp chunk double-buffering
// Numerics bit-identical to R16 (rel_err tripwire: 6.365884e-4).

#define S_LEN 2048
#define D_DIM 1024
#define HS    64
#define BH    32
#define MROWS 4096

// ---------------- scratch (no allocs allowed) ----------------
__device__ __half g_Kh[BH * S_LEN * HS];       // [B,H,S,HS] fp16
__device__ __half g_Ah[MROWS * D_DIM];         // Vcat: [b,s,(h,e)] fp16
__device__ __half g_Xh[MROWS * D_DIM];         // x fp16
__device__ __half g_Wth[2048 * 1024];          // [Wk|Wv] K-major rows
__device__ __half g_Wpth[1024 * 1024];         // Wproj^T K-major rows
__device__ __half g_Gt[2 * 1024 * 1024];       // G[b]: rows n, k=(h,e)

// =============================================================
// helpers
// =============================================================
__device__ __forceinline__ unsigned smem_u32(const void* p) {
    unsigned a;
    asm("{ .reg .u64 t; cvta.to.shared.u64 t, %1; cvt.u32.u64 %0, t; }"
        : "=r"(a) : "l"(p));
    return a;
}

__device__ __forceinline__ void cp16(void* dst, const void* src) {
    unsigned d;
    asm("{ .reg .u64 t; cvta.to.shared.u64 t, %1; cvt.u32.u64 %0, t; }"
        : "=r"(d) : "l"(dst));
    asm volatile("cp.async.cg.shared.global [%0], [%1], 16;" :: "r"(d), "l"(src));
}

__device__ __forceinline__ void ldsm4(unsigned* r, unsigned addr) {
    asm volatile("ldmatrix.sync.aligned.m8n8.x4.shared.b16 {%0,%1,%2,%3}, [%4];"
        : "=r"(r[0]), "=r"(r[1]), "=r"(r[2]), "=r"(r[3]) : "r"(addr));
}

__device__ __forceinline__ void ldsm4t(unsigned* r, unsigned addr) {
    asm volatile("ldmatrix.sync.aligned.m8n8.x4.trans.shared.b16 {%0,%1,%2,%3}, [%4];"
        : "=r"(r[0]), "=r"(r[1]), "=r"(r[2]), "=r"(r[3]) : "r"(addr));
}

__device__ __forceinline__ void mma16(float* d, const unsigned* a, const unsigned* b) {
    asm volatile(
        "mma.sync.aligned.m16n8k16.row.col.f32.f16.f16.f32 "
        "{%0,%1,%2,%3}, {%4,%5,%6,%7}, {%8,%9}, {%0,%1,%2,%3};"
        : "+f"(d[0]), "+f"(d[1]), "+f"(d[2]), "+f"(d[3])
        : "r"(a[0]), "r"(a[1]), "r"(a[2]), "r"(a[3]), "r"(b[0]), "r"(b[1]));
}

__device__ __forceinline__ void pdl_wait() {
#if __CUDA_ARCH__ >= 900
    cudaGridDependencySynchronize();
#endif
}
__device__ __forceinline__ void pdl_trigger() {
#if __CUDA_ARCH__ >= 900
    cudaTriggerProgrammaticLaunchCompletion();
#endif
}

// =============================================================
// prep: fused xcvt + tW + tWp, dispatched by block range. Natural fp16.
// =============================================================
__global__ __launch_bounds__(256) void prep(const float* __restrict__ x,
                                            const float* __restrict__ Wk,
                                            const float* __restrict__ Wv,
                                            const float* __restrict__ Wp)
{
    __shared__ float tile[32][33];
    const int blk = blockIdx.x, tid = threadIdx.x;
    pdl_trigger();                          // let gemm0 begin launching

    if (blk < 1024) {                       // ---- x -> fp16 ----
        int base = (blk * 256 + tid) * 16;
        float v[16];
        #pragma unroll
        for (int i = 0; i < 4; i++)
            *(float4*)(v + 4 * i) = *(const float4*)(x + base + 4 * i);
        __half2 out[8];
        #pragma unroll
        for (int p = 0; p < 8; p++)
            out[p] = __floats2half2_rn(v[2 * p], v[2 * p + 1]);
        *(uint4*)(g_Xh + base)     = ((uint4*)out)[0];
        *(uint4*)(g_Xh + base + 8) = ((uint4*)out)[1];
    } else if (blk < 3072) {                // ---- tW ----
        const int local = blk - 1024;
        const int bx = local & 31, by = (local >> 5) & 1, hh = local >> 6;
        const int x0 = bx * 32, y0 = by * 32;
        const int tx = tid & 31, ty = tid >> 5;
        const float* W = (hh < 16) ? Wk : Wv;
        const int h = hh & 15;
        #pragma unroll
        for (int j = 0; j < 4; j++)
            tile[ty + 8 * j][tx] = W[h * 65536 + (x0 + ty + 8 * j) * 64 + y0 + tx];
        __syncthreads();
        #pragma unroll
        for (int j = 0; j < 4; j++)
            g_Wth[(hh * 64 + y0 + ty + 8 * j) * 1024 + x0 + tx] =
                __float2half_rn(tile[tx][ty + 8 * j]);
    } else {                                // ---- tWp ----
        const int local = blk - 3072;
        const int bx = local & 31, by = local >> 5;
        const int x0 = bx * 32, y0 = by * 32;
        const int tx = tid & 31, ty = tid >> 5;
        #pragma unroll
        for (int j = 0; j < 4; j++)
            tile[ty + 8 * j][tx] = Wp[(y0 + ty + 8 * j) * 1024 + x0 + tx];
        __syncthreads();
        #pragma unroll
        for (int j = 0; j < 4; j++)
            g_Wpth[(x0 + ty + 8 * j) * 1024 + y0 + tx] =
                __float2half_rn(tile[tx][ty + 8 * j]);
    }
}

// =============================================================
// fp16 mma.sync GEMM (R16 core, + PDL wait/trigger)
// BM=128, BN=128, BK=64 halves, 3-stage, occ-2.
// mode 0: A=g_Xh, B=g_Wth; epilogue scatters K + Vcat.
// mode 1: A=g_Ah (Vcat), B=g_Gt[b], writes Y + bias.
// =============================================================
#define BMt 128
#define BNt 128
#define BKh 64
#define PITCHB 144
#define SA_BYTES (BMt * PITCHB)
#define SB_BYTES (BNt * PITCHB)
#define STAGE_BYTES (SA_BYTES + SB_BYTES)
#define GEMM_SMEM (3 * STAGE_BYTES)             // 110592

__global__ __launch_bounds__(256, 2)
void gemm_mma(const float* __restrict__ bias,
              float* __restrict__ Y,
              int mode)
{
    extern __shared__ __align__(16) char sm[];
    const int tid = threadIdx.x, wid = tid >> 5, lane = tid & 31;
    const int g = lane >> 2, tg = lane & 3;
    const int bm = blockIdx.y * BMt, bn = blockIdx.x * BNt;
    const unsigned smbase = smem_u32(sm);

    const __half* Ag = ((mode == 0) ? g_Xh : g_Ah) + (size_t)bm * 1024;
    const __half* Bg = ((mode == 0) ? g_Wth
                                    : g_Gt + (size_t)(bm >> 11) * 1048576)
                       + (size_t)bn * 1024;

    auto prefetch = [&](int kc) {
        char* sA = sm + (kc % 3) * STAGE_BYTES;
        char* sB = sA + SA_BYTES;
        const __half* As = Ag + kc * BKh;
        const __half* Bs = Bg + kc * BKh;
        #pragma unroll
        for (int i = 0; i < 4; i++) {
            int idx = tid + i * 256;
            int m = idx >> 3, c8 = idx & 7;
            cp16(sA + m * PITCHB + c8 * 16, As + (size_t)m * 1024 + c8 * 8);
        }
        #pragma unroll
        for (int i = 0; i < 4; i++) {
            int idx = tid + i * 256;
            int n = idx >> 3, c8 = idx & 7;
            cp16(sB + n * PITCHB + c8 * 16, Bs + (size_t)n * 1024 + c8 * 8);
        }
        asm volatile("cp.async.commit_group;" ::: "memory");
    };

    pdl_wait();                              // producer data must be visible
    prefetch(0); prefetch(1);

    const int wm = (wid & 1) * 64;       // 2 warps along M (64 rows)
    const int wn = (wid >> 1) * 32;      // 4 warps along N (32 cols)

    const int j8  = lane & 7, grp = lane >> 3;
    const int arow = (grp & 1) * 8 + j8;
    const int acol = (grp >> 1) * 8;
    const int brow = (grp >> 1) * 8 + j8;
    const int bcol = (grp & 1) * 8;

    float acc[4][4][4];
    #pragma unroll
    for (int mt = 0; mt < 4; mt++)
        #pragma unroll
        for (int nt = 0; nt < 4; nt++)
            #pragma unroll
            for (int q = 0; q < 4; q++) acc[mt][nt][q] = 0.f;

    for (int kc = 0; kc < 16; kc++) {
        const unsigned sAu = smbase + (kc % 3) * STAGE_BYTES;
        const unsigned sBu = sAu + SA_BYTES;
        if (kc < 15) asm volatile("cp.async.wait_group 1;" ::: "memory");
        else         asm volatile("cp.async.wait_group 0;" ::: "memory");
        __syncthreads();
        if (kc + 2 < 16) prefetch(kc + 2);

        #pragma unroll
        for (int ks = 0; ks < 4; ks++) {
            const int k0 = ks * 16;
            unsigned a[4][4], bq[2][4];
            #pragma unroll
            for (int mt = 0; mt < 4; mt++)
                ldsm4(a[mt], sAu + (wm + mt * 16 + arow) * PITCHB + (k0 + acol) * 2);
            #pragma unroll
            for (int p = 0; p < 2; p++)
                ldsm4(bq[p], sBu + (wn + p * 16 + brow) * PITCHB + (k0 + bcol) * 2);
            #pragma unroll
            for (int mt = 0; mt < 4; mt++)
                #pragma unroll
                for (int nt = 0; nt < 4; nt++)
                    mma16(acc[mt][nt], a[mt], &bq[nt >> 1][(nt & 1) * 2]);
        }
    }

    pdl_trigger();                           // overlap successor launch w/ epilogue

    // ---- epilogue ----
    const int gnw = bn + wn;                 // 32-aligned, inside one head
    if (mode == 0) {
        const int isK = (gnw < 1024);
        const int h  = (gnw & 1023) >> 6;
        const int e0 = gnw & 63;
        #pragma unroll
        for (int mt = 0; mt < 4; mt++) {
            const int m0 = bm + wm + mt * 16 + g;
            #pragma unroll
            for (int half = 0; half < 2; half++) {
                const int m = m0 + half * 8;
                const int b = m >> 11, s = m & 2047;
                __half* dst = isK
                    ? (g_Kh + (size_t)((b * 16 + h) * 2048 + s) * 64 + e0)
                    : (g_Ah + (size_t)(b * 2048 + s) * 1024 + h * 64 + e0);
                #pragma unroll
                for (int nt = 0; nt < 4; nt++) {
                    const int e = nt * 8 + tg * 2;
                    *(__half2*)(dst + e) =
                        __floats2half2_rn(acc[mt][nt][half * 2],
                                          acc[mt][nt][half * 2 + 1]);
                }
            }
        }
    } else {
        #pragma unroll
        for (int mt = 0; mt < 4; mt++) {
            const int m0 = bm + wm + mt * 16 + g;
            #pragma unroll
            for (int half = 0; half < 2; half++) {
                const int m = m0 + half * 8;
                float* dst = Y + (size_t)m * 1024;
                #pragma unroll
                for (int nt = 0; nt < 4; nt++) {
                    const int gn = gnw + nt * 8 + tg * 2;
                    float2 bb = *(const float2*)(bias + gn);
                    *(float2*)(dst + gn) = make_float2(acc[mt][nt][half * 2] + bb.x,
                                                       acc[mt][nt][half * 2 + 1] + bb.y);
                }
            }
        }
    }
}

// =============================================================
// k_mg: one CTA per (b,h).
// Phase 1: M[e,f] = (1/8) sum_s K[s,e] V[s,f]  via ldmatrix.trans (k = s).
// Phase 2: G[b][n, h*64+e] = sum_f Wp^T[n, h64+f] M[e,f]; 4 n-chunks of 256,
//          now DOUBLE-BUFFERED (2 x 36KB ping-pong; M region moved above).
// =============================================================
#define MGP 144
#define KV_BUF 18432
#define WP_BUF 36864
#define SM_M  (2 * WP_BUF)                      // 73728
#define MG_SMEM (SM_M + 9216)                   // 82944

__global__ __launch_bounds__(256, 1) void k_mg()
{
    extern __shared__ __align__(16) char smE[];
    const int bh = blockIdx.x;
    const int b = bh >> 4, h = bh & 15;
    const int tid = threadIdx.x, wid = tid >> 5, lane = tid & 31;
    const int g = lane >> 2, tg = lane & 3;
    const int j8 = lane & 7, grp = lane >> 3;
    const unsigned smbase = smem_u32(smE);

    const __half* Kb = g_Kh + (size_t)bh * S_LEN * HS;
    const __half* Vb = g_Ah + (size_t)b * S_LEN * 1024 + h * 64;

    auto prefetch_kv = [&](int sc) {
        char* base = smE + (sc % 3) * KV_BUF;
        #pragma unroll
        for (int i = 0; i < 4; i++) {
            int idx = tid + i * 256;
            int mat = idx >> 9, rc = idx & 511;
            int r = rc >> 3, c8 = rc & 7;
            if (mat == 0)
                cp16(base + r * MGP + c8 * 16,
                     Kb + (size_t)(sc * 64 + r) * 64 + c8 * 8);
            else
                cp16(base + 9216 + r * MGP + c8 * 16,
                     Vb + (size_t)(sc * 64 + r) * 1024 + c8 * 8);
        }
        asm volatile("cp.async.commit_group;" ::: "memory");
    };

    pdl_wait();                              // K / Vcat must be complete
    prefetch_kv(0); prefetch_kv(1);

    const int we = (wid & 3) * 16;
    const int wf = (wid >> 2) * 32;
    const int a_s = (grp >> 1) * 8 + j8, a_e = (grp & 1) * 8;
    const int b_s = (grp & 1) * 8 + j8, b_f = (grp >> 1) * 8;

    float accM[4][4];
    #pragma unroll
    for (int nt = 0; nt < 4; nt++)
        #pragma unroll
        for (int q = 0; q < 4; q++) accM[nt][q] = 0.f;

    for (int sc = 0; sc < 32; sc++) {
        const unsigned sK = smbase + (sc % 3) * KV_BUF;
        const unsigned sV = sK + 9216;
        if (sc < 31) asm volatile("cp.async.wait_group 1;" ::: "memory");
        else         asm volatile("cp.async.wait_group 0;" ::: "memory");
        __syncthreads();
        if (sc + 2 < 32) prefetch_kv(sc + 2);

        #pragma unroll
        for (int ks = 0; ks < 4; ks++) {
            const int s0 = ks * 16;
            unsigned a[4], bq[2][4];
            ldsm4t(a, sK + (s0 + a_s) * MGP + (we + a_e) * 2);
            #pragma unroll
            for (int p = 0; p < 2; p++)
                ldsm4t(bq[p], sV + (s0 + b_s) * MGP + (wf + p * 16 + b_f) * 2);
            #pragma unroll
            for (int nt = 0; nt < 4; nt++)
                mma16(accM[nt], a, &bq[nt >> 1][(nt & 1) * 2]);
        }
    }

    {
        char* sM = smE + SM_M;
        #pragma unroll
        for (int nt = 0; nt < 4; nt++)
            #pragma unroll
            for (int half = 0; half < 2; half++) {
                const int e = we + g + half * 8;
                const int f = wf + nt * 8 + tg * 2;
                *(__half2*)(sM + e * MGP + f * 2) =
                    __floats2half2_rn(accM[nt][half * 2] * 0.125f,
                                      accM[nt][half * 2 + 1] * 0.125f);
            }
    }
    __syncthreads();

    // ---------------- phase 2: G = Wp^T-rows @ M (double-buffered) --------
    const __half* Wpb = g_Wpth + h * 64;
    __half* Gb = g_Gt + (size_t)b * 1048576 + h * 64;
    const unsigned sMu = smbase + SM_M;

    const int wm = (wid & 3) * 64;
    const int wn = (wid >> 2) * 32;
    const int arow = (grp & 1) * 8 + j8, acol = (grp >> 1) * 8;
    const int brow = (grp >> 1) * 8 + j8, bcol = (grp & 1) * 8;

    auto stage_wp = [&](int nc) {
        char* dst = smE + (nc & 1) * WP_BUF;
        #pragma unroll
        for (int i = 0; i < 8; i++) {
            int idx = tid + i * 256;
            int r = idx >> 3, c8 = idx & 7;
            cp16(dst + r * MGP + c8 * 16,
                 Wpb + (size_t)(nc * 256 + r) * 1024 + c8 * 8);
        }
        asm volatile("cp.async.commit_group;" ::: "memory");
    };

    stage_wp(0);
    pdl_trigger();                           // mode1 may begin launching

    for (int nc = 0; nc < 4; nc++) {
        if (nc < 3) stage_wp(nc + 1);
        if (nc < 3) asm volatile("cp.async.wait_group 1;" ::: "memory");
        else        asm volatile("cp.async.wait_group 0;" ::: "memory");
        __syncthreads();

        const unsigned sW = smbase + (nc & 1) * WP_BUF;

        float acc2[4][4][4];
        #pragma unroll
        for (int mt = 0; mt < 4; mt++)
            #pragma unroll
            for (int nt = 0; nt < 4; nt++)
                #pragma unroll
                for (int q = 0; q < 4; q++) acc2[mt][nt][q] = 0.f;

        #pragma unroll
        for (int ks = 0; ks < 4; ks++) {
            const int k0 = ks * 16;
            unsigned a[4][4], bq[2][4];
            #pragma unroll
            for (int mt = 0; mt < 4; mt++)
                ldsm4(a[mt], sW + (wm + mt * 16 + arow) * MGP + (k0 + acol) * 2);
            #pragma unroll
            for (int p = 0; p < 2; p++)
                ldsm4(bq[p], sMu + (wn + p * 16 + brow) * MGP + (k0 + bcol) * 2);
            #pragma unroll
            for (int mt = 0; mt < 4; mt++)
                #pragma unroll
                for (int nt = 0; nt < 4; nt++)
                    mma16(acc2[mt][nt], a[mt], &bq[nt >> 1][(nt & 1) * 2]);
        }

        #pragma unroll
        for (int mt = 0; mt < 4; mt++) {
            const int n0 = nc * 256 + wm + mt * 16 + g;
            #pragma unroll
            for (int half = 0; half < 2; half++) {
                __half* dst = Gb + (size_t)(n0 + half * 8) * 1024;
                #pragma unroll
                for (int nt = 0; nt < 4; nt++) {
                    const int e = wn + nt * 8 + tg * 2;
                    *(__half2*)(dst + e) =
                        __floats2half2_rn(acc2[mt][nt][half * 2],
                                          acc2[mt][nt][half * 2 + 1]);
                }
            }
        }
        __syncthreads();
    }
}

// =============================================================
extern "C" void kernel_launch(void* const* d_in, const int* in_sizes, int n_in,
                              void* d_out, int out_size)
{
    const float* x   = (const float*)d_in[0];
    const float* Wk  = (const float*)d_in[1];
    const float* Wv  = (const float*)d_in[2];
    const float* Wp  = (const float*)d_in[3];
    const float* bp  = (const float*)d_in[4];
    float* Y = (float*)d_out;

    cudaFuncSetAttribute(gemm_mma, cudaFuncAttributeMaxDynamicSharedMemorySize, GEMM_SMEM);
    cudaFuncSetAttribute(k_mg, cudaFuncAttributeMaxDynamicSharedMemorySize, MG_SMEM);

    prep<<<4096, 256>>>(x, Wk, Wv, Wp);

    cudaLaunchAttribute attr[1];
    attr[0].id = cudaLaunchAttributeProgrammaticStreamSerialization;
    attr[0].val.programmaticStreamSerializationAllowed = 1;

    {   // gemm mode0: K + Vcat (depends on prep)
        cudaLaunchConfig_t cfg = {};
        cfg.gridDim = dim3(16, 32, 1);
        cfg.blockDim = dim3(256, 1, 1);
        cfg.dynamicSmemBytes = GEMM_SMEM;
        cfg.attrs = attr; cfg.numAttrs = 1;
        cudaLaunchKernelEx(&cfg, gemm_mma, bp, Y, 0);
    }
    {   // k_mg: M then G (depends on mode0)
        cudaLaunchConfig_t cfg = {};
        cfg.gridDim = dim3(32, 1, 1);
        cfg.blockDim = dim3(256, 1, 1);
        cfg.dynamicSmemBytes = MG_SMEM;
        cfg.attrs = attr; cfg.numAttrs = 1;
        cudaLaunchKernelEx(&cfg, k_mg);
    }
    {   // gemm mode1: Y = Vcat@G + b (depends on k_mg)
        cudaLaunchConfig_t cfg = {};
        cfg.gridDim = dim3(8, 32, 1);
        cfg.blockDim = dim3(256, 1, 1);
        cfg.dynamicSmemBytes = GEMM_SMEM;
        cfg.attrs = attr; cfg.numAttrs = 1;
        cudaLaunchKernelEx(&cfg, gemm_mma, bp, Y, 1);
    }
}